// round 1
// baseline (speedup 1.0000x reference)
#include <cuda_runtime.h>
#include <math.h>

// Problem constants (fixed-shape problem)
#define BB   16
#define NN   2048
#define DD   64
#define EE   32768
#define MAXK 256
#define ROWS (BB*NN)          // 32768

// Scratch (device globals; no allocation in kernel_launch)
__device__ int      g_cnt[ROWS];
__device__ unsigned g_bucket[(size_t)ROWS * MAXK];   // 32 MB
__device__ float    g_dis[ROWS];
__device__ float    g_x1[(size_t)ROWS * DD];         // 8 MB ping buffer

// ---------------------------------------------------------------------------
// 1) zero row counters
__global__ void zero_cnt_k() {
    int t = blockIdx.x * blockDim.x + threadIdx.x;
    if (t < ROWS) g_cnt[t] = 0;
}

// ---------------------------------------------------------------------------
// 2) scatter directed entries into per-row buckets
//    entry = (col << 17) | priority, priority = pass*E + e
//    pass1: row=src, col=dst ; pass2: row=dst, col=src (pass2 overwrites pass1)
__global__ void scatter_k(const int* __restrict__ ei) {
    int t = blockIdx.x * blockDim.x + threadIdx.x;
    if (t >= BB * EE) return;
    int b = t >> 15;            // / EE
    int e = t & (EE - 1);
    int src = ei[b * 2 * EE + e];
    int dst = ei[b * 2 * EE + EE + e];

    int r1 = b * NN + src;
    int p1 = atomicAdd(&g_cnt[r1], 1);
    if (p1 < MAXK) g_bucket[(size_t)r1 * MAXK + p1] = ((unsigned)dst << 17) | (unsigned)e;

    int r2 = b * NN + dst;
    int p2 = atomicAdd(&g_cnt[r2], 1);
    if (p2 < MAXK) g_bucket[(size_t)r2 * MAXK + p2] = ((unsigned)src << 17) | (unsigned)(EE + e);
}

// ---------------------------------------------------------------------------
// 3) per-row dedup (exact scatter-set semantics: keep max priority per col),
//    in-place compaction, degree -> dis = rsqrt(deg)
__global__ void __launch_bounds__(128) dedup_k(const float* __restrict__ m) {
    int row = blockIdx.x;
    int b = row >> 11;          // / NN
    __shared__ unsigned s[MAXK];
    __shared__ int pos;
    __shared__ float wsum[4];

    int k = g_cnt[row];
    if (k > MAXK) k = MAXK;
    for (int t = threadIdx.x; t < k; t += 128)
        s[t] = g_bucket[(size_t)row * MAXK + t];
    if (threadIdx.x == 0) pos = 0;
    __syncthreads();

    float local = 0.f;
    for (int t = threadIdx.x; t < k; t += 128) {
        unsigned v = s[t];
        unsigned col = v >> 17;
        bool keep = true;
        for (int u = 0; u < k; u++) {
            unsigned w = s[u];
            if (w > v && (w >> 17) == col) { keep = false; break; }
        }
        if (keep) {
            int p = atomicAdd(&pos, 1);
            g_bucket[(size_t)row * MAXK + p] = v;
            local += m[b * EE + (int)(v & (EE - 1))];  // e = pri & (E-1)
        }
    }
    // block reduction of local
    unsigned lane = threadIdx.x & 31, wid = threadIdx.x >> 5;
    #pragma unroll
    for (int o = 16; o; o >>= 1) local += __shfl_down_sync(0xFFFFFFFFu, local, o);
    if (lane == 0) wsum[wid] = local;
    __syncthreads();
    if (threadIdx.x == 0) {
        float deg = 1.0f + wsum[0] + wsum[1] + wsum[2] + wsum[3];
        g_cnt[row] = pos;
        g_dis[row] = rsqrtf(fmaxf(deg, 1e-6f));
    }
}

// ---------------------------------------------------------------------------
// 4) fused layer: x1 = A_norm @ X (sparse, + identity diag), out = x1 @ W^T,
//    optional exact GELU. Warp per row, 4 rows/warp, W^T staged in smem.
__global__ void __launch_bounds__(256) layer_k(const float* __restrict__ Xin_p,
                                               const float* __restrict__ m,
                                               const float* __restrict__ Wl,
                                               float* __restrict__ Xout_p,
                                               int apply_gelu) {
    const float* Xin = Xin_p ? Xin_p : g_x1;
    float*       Xout = Xout_p ? Xout_p : g_x1;

    __shared__ float sW[64 * 64];   // sW[d*64+e] = W[e*64+d]
    __shared__ float sx1[8 * 64];

    int tid = threadIdx.x;
    for (int idx = tid; idx < 4096; idx += 256) {
        int e = idx >> 6, d = idx & 63;
        sW[d * 64 + e] = Wl[idx];   // coalesced global read
    }
    __syncthreads();

    int wid = tid >> 5, lane = tid & 31;
    int row_base = blockIdx.x * 32 + wid * 4;

    for (int r = 0; r < 4; r++) {
        int row = row_base + r;
        int b   = row >> 11;
        int nb  = b << 11;               // b*NN
        int gbase = row * 64;
        float dis_i = g_dis[row];
        int nnz = g_cnt[row];
        const unsigned* bk = &g_bucket[(size_t)row * MAXK];

        float a0 = 0.f, a1 = 0.f;
        for (int k = 0; k < nnz; k++) {
            unsigned v = bk[k];
            int col = v >> 17;
            int e   = v & (EE - 1);
            float coeff = m[b * EE + e] * g_dis[nb + col];
            const float* xr = Xin + (size_t)(nb + col) * 64;
            a0 += coeff * xr[lane];
            a1 += coeff * xr[lane + 32];
        }
        float x0 = dis_i * a0 + dis_i * dis_i * Xin[gbase + lane];
        float x1 = dis_i * a1 + dis_i * dis_i * Xin[gbase + lane + 32];

        sx1[wid * 64 + lane]      = x0;
        sx1[wid * 64 + lane + 32] = x1;
        __syncwarp();

        const float* xs = &sx1[wid * 64];
        float o0 = 0.f, o1 = 0.f;
        #pragma unroll
        for (int d = 0; d < 64; d++) {
            float xv = xs[d];
            o0 += xv * sW[d * 64 + lane];
            o1 += xv * sW[d * 64 + lane + 32];
        }
        if (apply_gelu) {
            o0 = 0.5f * o0 * (1.f + erff(o0 * 0.70710678118654752f));
            o1 = 0.5f * o1 * (1.f + erff(o1 * 0.70710678118654752f));
        }
        Xout[gbase + lane]      = o0;
        Xout[gbase + lane + 32] = o1;
        __syncwarp();   // sx1 region reused next r within this warp
    }
}

// ---------------------------------------------------------------------------
extern "C" void kernel_launch(void* const* d_in, const int* in_sizes, int n_in,
                              void* d_out, int out_size) {
    const float* H  = (const float*)d_in[0];
    const int*   ei = (const int*)  d_in[1];
    const float* m  = (const float*)d_in[2];
    const float* W  = (const float*)d_in[3];
    float* out = (float*)d_out;

    zero_cnt_k<<<(ROWS + 255) / 256, 256>>>();
    scatter_k<<<(BB * EE + 255) / 256, 256>>>(ei);
    dedup_k<<<ROWS, 128>>>(m);
    // layer 0: H -> g_x1 (Xout = nullptr selects g_x1), with GELU
    layer_k<<<ROWS / 32, 256>>>(H, m, W, nullptr, 1);
    // layer 1: g_x1 -> out, no activation
    layer_k<<<ROWS / 32, 256>>>(nullptr, m, W + 64 * 64, out, 0);
}

// round 2
// speedup vs baseline: 1.0303x; 1.0303x over previous
#include <cuda_runtime.h>
#include <math.h>

// Problem constants (fixed-shape problem)
#define BB   16
#define NN   2048
#define DD   64
#define EE   32768
#define MAXK 256
#define ROWS (BB*NN)          // 32768

// Scratch (device globals; no allocation anywhere)
__device__ int      g_cnt[ROWS];
__device__ unsigned g_bucket[(size_t)ROWS * MAXK];   // 32 MB (col<<17 | pri)
__device__ float    g_dis[ROWS];
__device__ float    g_diag[ROWS];
__device__ uint2    g_adj[(size_t)ROWS * MAXK];      // 64 MB (col, w)
__device__ float    g_x1[(size_t)ROWS * DD];         // 8 MB ping buffer

// ---------------------------------------------------------------------------
__global__ void zero_cnt_k() {
    int t = blockIdx.x * blockDim.x + threadIdx.x;
    if (t < ROWS) g_cnt[t] = 0;
}

// ---------------------------------------------------------------------------
// scatter directed entries into per-row buckets
// entry = (col << 17) | priority, priority = pass*E + e (pass2 overwrites pass1)
__global__ void scatter_k(const int* __restrict__ ei) {
    int t = blockIdx.x * blockDim.x + threadIdx.x;
    if (t >= BB * EE) return;
    int b = t >> 15;
    int e = t & (EE - 1);
    int src = ei[b * 2 * EE + e];
    int dst = ei[b * 2 * EE + EE + e];

    int r1 = b * NN + src;
    int p1 = atomicAdd(&g_cnt[r1], 1);
    if (p1 < MAXK) g_bucket[(size_t)r1 * MAXK + p1] = ((unsigned)dst << 17) | (unsigned)e;

    int r2 = b * NN + dst;
    int p2 = atomicAdd(&g_cnt[r2], 1);
    if (p2 < MAXK) g_bucket[(size_t)r2 * MAXK + p2] = ((unsigned)src << 17) | (unsigned)(EE + e);
}

// ---------------------------------------------------------------------------
// per-row dedup (exact scatter-set semantics: keep max priority per col),
// in-place compaction, degree -> dis = rsqrt(deg)
__global__ void __launch_bounds__(128) dedup_k(const float* __restrict__ m) {
    int row = blockIdx.x;
    int b = row >> 11;
    __shared__ unsigned s[MAXK];
    __shared__ int pos;
    __shared__ float wsum[4];

    int k = g_cnt[row];
    if (k > MAXK) k = MAXK;
    for (int t = threadIdx.x; t < k; t += 128)
        s[t] = g_bucket[(size_t)row * MAXK + t];
    if (threadIdx.x == 0) pos = 0;
    __syncthreads();

    float local = 0.f;
    for (int t = threadIdx.x; t < k; t += 128) {
        unsigned v = s[t];
        unsigned col = v >> 17;
        bool keep = true;
        for (int u = 0; u < k; u++) {
            unsigned w = s[u];
            if (w > v && (w >> 17) == col) { keep = false; break; }
        }
        if (keep) {
            int p = atomicAdd(&pos, 1);
            g_bucket[(size_t)row * MAXK + p] = v;
            local += m[b * EE + (int)(v & (EE - 1))];
        }
    }
    unsigned lane = threadIdx.x & 31, wid = threadIdx.x >> 5;
    #pragma unroll
    for (int o = 16; o; o >>= 1) local += __shfl_down_sync(0xFFFFFFFFu, local, o);
    if (lane == 0) wsum[wid] = local;
    __syncthreads();
    if (threadIdx.x == 0) {
        float deg = 1.0f + wsum[0] + wsum[1] + wsum[2] + wsum[3];
        g_cnt[row] = pos;
        g_dis[row] = rsqrtf(fmaxf(deg, 1e-6f));
    }
}

// ---------------------------------------------------------------------------
// finalize: convert compacted (col, e) entries into (col, w) CSR with
// w = m[b,e] * dis[row] * dis[col];  g_diag[row] = dis[row]^2.
// One warp per row.
__global__ void __launch_bounds__(256) finalize_k(const float* __restrict__ m) {
    int row = blockIdx.x * 8 + (threadIdx.x >> 5);
    int lane = threadIdx.x & 31;
    int b = row >> 11;
    int nb = row & ~(NN - 1);
    int nnz = g_cnt[row];
    float disr = g_dis[row];
    for (int k = lane; k < nnz; k += 32) {
        unsigned v = g_bucket[(size_t)row * MAXK + k];
        int col = (int)(v >> 17);
        int e   = (int)(v & (EE - 1));
        float w = m[b * EE + e] * disr * g_dis[nb + col];
        g_adj[(size_t)row * MAXK + k] = make_uint2((unsigned)col, __float_as_uint(w));
    }
    if (lane == 0) g_diag[row] = disr * disr;
}

// ---------------------------------------------------------------------------
// fused layer: x1 = A_norm @ X (sparse + diag), out = x1 @ W^T, optional GELU.
// Warp per 4 rows; lane owns feature pair {2l, 2l+1}; float2 gathers,
// 4x-unrolled gather loop; GEMM amortizes W LDS over 4 rows via shuffles.
__global__ void __launch_bounds__(256) layer_k(const float* __restrict__ Xin_p,
                                               const float* __restrict__ Wl,
                                               float* __restrict__ Xout_p,
                                               int apply_gelu) {
    const float* Xin  = Xin_p  ? Xin_p  : g_x1;
    float*       Xout = Xout_p ? Xout_p : g_x1;

    // sW[d*32 + j] = {W[2j][d], W[2j+1][d]}
    __shared__ float2 sW[64 * 32];
    int tid = threadIdx.x;
    for (int idx = tid; idx < 4096; idx += 256) {
        int e = idx >> 6, d = idx & 63;
        ((float*)&sW[d * 32 + (e >> 1)])[e & 1] = Wl[idx];  // coalesced read
    }
    __syncthreads();

    int wid = tid >> 5, lane = tid & 31;
    int row0 = blockIdx.x * 32 + wid * 4;

    float2 acc[4];
    #pragma unroll
    for (int r = 0; r < 4; r++) {
        int row = row0 + r;
        int nb  = row & ~(NN - 1);
        const float2* Xb = (const float2*)(Xin + (size_t)nb * DD);
        const float2* Xr = (const float2*)(Xin + (size_t)row * DD);

        float dg = g_diag[row];
        float2 xo = Xr[lane];
        float2 a; a.x = dg * xo.x; a.y = dg * xo.y;

        int nnz = g_cnt[row];
        const uint2* adj = &g_adj[(size_t)row * MAXK];
        int k = 0;
        for (; k + 4 <= nnz; k += 4) {
            uint2 e0 = __ldg(&adj[k]);
            uint2 e1 = __ldg(&adj[k + 1]);
            uint2 e2 = __ldg(&adj[k + 2]);
            uint2 e3 = __ldg(&adj[k + 3]);
            float2 x0 = Xb[(size_t)e0.x * 32 + lane];
            float2 x1 = Xb[(size_t)e1.x * 32 + lane];
            float2 x2 = Xb[(size_t)e2.x * 32 + lane];
            float2 x3 = Xb[(size_t)e3.x * 32 + lane];
            float w0 = __uint_as_float(e0.y);
            float w1 = __uint_as_float(e1.y);
            float w2 = __uint_as_float(e2.y);
            float w3 = __uint_as_float(e3.y);
            a.x += w0 * x0.x; a.y += w0 * x0.y;
            a.x += w1 * x1.x; a.y += w1 * x1.y;
            a.x += w2 * x2.x; a.y += w2 * x2.y;
            a.x += w3 * x3.x; a.y += w3 * x3.y;
        }
        for (; k < nnz; k++) {
            uint2 en = __ldg(&adj[k]);
            float2 xv = Xb[(size_t)en.x * 32 + lane];
            float w = __uint_as_float(en.y);
            a.x += w * xv.x; a.y += w * xv.y;
        }
        acc[r] = a;
    }

    // GEMM: out[row][e] = sum_d x1[row][d] * W[e][d]; lane owns e = {2l, 2l+1}
    float2 o[4];
    #pragma unroll
    for (int r = 0; r < 4; r++) { o[r].x = 0.f; o[r].y = 0.f; }

    #pragma unroll
    for (int d = 0; d < 64; d++) {
        float2 w2 = sW[d * 32 + lane];
        int srcl = d >> 1;
        #pragma unroll
        for (int r = 0; r < 4; r++) {
            float xd = __shfl_sync(0xFFFFFFFFu, (d & 1) ? acc[r].y : acc[r].x, srcl);
            o[r].x += xd * w2.x;
            o[r].y += xd * w2.y;
        }
    }

    #pragma unroll
    for (int r = 0; r < 4; r++) {
        float2 v = o[r];
        if (apply_gelu) {
            v.x = 0.5f * v.x * (1.f + erff(v.x * 0.70710678118654752f));
            v.y = 0.5f * v.y * (1.f + erff(v.y * 0.70710678118654752f));
        }
        ((float2*)(Xout + (size_t)(row0 + r) * DD))[lane] = v;
    }
}

// ---------------------------------------------------------------------------
extern "C" void kernel_launch(void* const* d_in, const int* in_sizes, int n_in,
                              void* d_out, int out_size) {
    const float* H  = (const float*)d_in[0];
    const int*   ei = (const int*)  d_in[1];
    const float* m  = (const float*)d_in[2];
    const float* W  = (const float*)d_in[3];
    float* out = (float*)d_out;

    zero_cnt_k<<<(ROWS + 255) / 256, 256>>>();
    scatter_k<<<(BB * EE + 255) / 256, 256>>>(ei);
    dedup_k<<<ROWS, 128>>>(m);
    finalize_k<<<ROWS / 8, 256>>>(m);
    layer_k<<<ROWS / 32, 256>>>(H, W, nullptr, 1);            // layer 0 -> g_x1, GELU
    layer_k<<<ROWS / 32, 256>>>(nullptr, W + DD * DD, out, 0); // layer 1 -> out
}